// round 6
// baseline (speedup 1.0000x reference)
#include <cuda_runtime.h>
#include <cuda_fp16.h>
#include <math.h>

// Problem constants (fixed by the dataset)
#define BB 32        // batch (== warp size, lane = batch index)
#define TT 400       // timesteps
#define PP 3500      // pdf dim
#define SS 2000      // FST states
#define EE 50000     // arcs
#define NBLK 250     // persistent blocks: 250*8 warps == 2000 states, co-resident (2/SM)
#define WPB 8        // warps per block
#define GMS 32       // float stride between per-(t,b) max slots -> one 128B line each

// ---------------- device scratch (static: no allocations allowed) ----------------
__device__ __half   g_ex[(size_t)TT * PP * BB];   // exp(x) transposed: [t][p][b], fp16 (~90MB)
__device__ __half   g_A[2][SS * BB];              // ping-pong linear-domain alpha, fp16
__device__ int2     g_meta[EE];                   // per arc (sorted by dst): {pdf*32, (src*32)|(fp16(tp)<<16)}
__device__ int      g_rowstart[SS + 1];
__device__ int      g_cnt[SS];
__device__ int      g_fill[SS];
__device__ float    g_maxP[(TT + 1) * BB * GMS];  // padded per-step per-batch max
__device__ unsigned g_bar;                        // grid barrier counter (monotonic per launch)

// L2-coherent fp16 load (A is written by other SMs between barrier phases; L1 not coherent)
__device__ __forceinline__ float ldcg_half(const __half* p) {
    unsigned short u = (unsigned short)__ldcg((const short*)p);
    __half_raw hr; hr.x = u;
    return __half2float(__half(hr));
}

__device__ __forceinline__ float ushort_as_half_f(unsigned short u) {
    __half_raw hr; hr.x = u;
    return __half2float(__half(hr));
}

// ---------------- preprocessing kernels ----------------
__global__ void k_zero() {
    int i = blockIdx.x * blockDim.x + threadIdx.x;
    int stride = gridDim.x * blockDim.x;
    for (int j = i; j < SS; j += stride) g_cnt[j] = 0;
    for (int j = i; j < (TT + 1) * BB * GMS; j += stride) g_maxP[j] = 0.f;
    if (i == 0) g_bar = 0u;
}

__global__ void k_hist(const int* __restrict__ dst) {
    int e = blockIdx.x * blockDim.x + threadIdx.x;
    if (e < EE) atomicAdd(&g_cnt[dst[e]], 1);
}

__global__ void k_scan() {   // single block, 256 threads, chunk=8
    __shared__ int ssum[256];
    __shared__ int soff[257];
    int tid = threadIdx.x;
    int b0 = tid * 8, b1 = min(b0 + 8, SS);
    int loc[8];
    int s = 0;
    for (int i = b0; i < b1; i++) { loc[i - b0] = s; s += g_cnt[i]; }
    ssum[tid] = s;
    __syncthreads();
    if (tid == 0) {
        int run = 0;
        for (int i = 0; i < 256; i++) { soff[i] = run; run += ssum[i]; }
        soff[256] = run;
    }
    __syncthreads();
    int base = soff[tid];
    for (int i = b0; i < b1; i++) {
        int v = base + loc[i - b0];
        g_rowstart[i] = v;
        g_fill[i] = v;
    }
    if (tid == 0) g_rowstart[SS] = soff[256];
}

__global__ void k_scatter(const int* __restrict__ src, const int* __restrict__ dst,
                          const int* __restrict__ pdf, const float* __restrict__ lw) {
    int e = blockIdx.x * blockDim.x + threadIdx.x;
    if (e < EE) {
        int d = dst[e];
        int pos = atomicAdd(&g_fill[d], 1);
        __half tph = __float2half(__expf(lw[e]));   // linear-domain transition prob, fp16
        __half_raw hr = __half_raw(tph);
        int2 m;
        m.x = pdf[e] * BB;
        m.y = (src[e] * BB) | ((int)hr.x << 16);    // src*32 <= 63968 fits in 16 bits
        g_meta[pos] = m;
    }
}

__global__ void k_initA(const float* __restrict__ ini) {
    int idx = blockIdx.x * 256 + threadIdx.x;     // exactly S*B threads
    int s = idx >> 5, lane = idx & 31;
    float v = __expf(ini[s]);
    g_A[0][s * BB + lane] = __float2half(v);
    __shared__ float sm[WPB][BB];
    sm[threadIdx.x >> 5][lane] = v;
    __syncthreads();
    if (threadIdx.x < 32) {
        float mx = sm[0][lane];
#pragma unroll
        for (int w = 1; w < WPB; w++) mx = fmaxf(mx, sm[w][lane]);
        atomicMax((unsigned*)&g_maxP[lane * GMS], __float_as_uint(mx));  // t=0 slot
    }
}

// transpose x[b][t][p] -> ex[t][p][b] = fp16(exp(x)), smem tiled
__global__ void k_texp(const float* __restrict__ x) {
    __shared__ float tile[32][33];
    int t = blockIdx.y;
    int p0 = blockIdx.x * 32;
    int tx = threadIdx.x;
    for (int bb = threadIdx.y; bb < 32; bb += 8) {
        int p = p0 + tx;
        tile[bb][tx] = (p < PP) ? x[(bb * TT + t) * PP + p] : 0.f;
    }
    __syncthreads();
    for (int pp = threadIdx.y; pp < 32; pp += 8) {
        int p = p0 + pp;
        if (p < PP)
            g_ex[((size_t)t * PP + p) * BB + tx] = __float2half(__expf(tile[tx][pp]));
    }
}

// ---------------- persistent main kernel: 400 steps with grid barrier ----------------
__global__ void __launch_bounds__(256, 2) k_main(float* __restrict__ out) {
    const int lane = threadIdx.x & 31;      // batch index
    const int wid = threadIdx.x >> 5;
    const int state = blockIdx.x * WPB + wid;   // exactly covers [0, 2000)
    __shared__ float sm[WPB][BB];

    const int r0 = g_rowstart[state];
    const int r1 = g_rowstart[state + 1];

    for (int t = 0; t < TT; t++) {
        const __half* __restrict__ Ain = g_A[t & 1];
        __half* __restrict__ Aout = g_A[(t + 1) & 1];
        const __half* __restrict__ exb = g_ex + (size_t)t * (PP * BB);
        float invm = 1.f / fmaxf(__ldcg(&g_maxP[(t * BB + lane) * GMS]), 1e-30f);

        float acc = 0.f;
#pragma unroll 4
        for (int a = r0; a < r1; a++) {
            int2 m = __ldg(&g_meta[a]);                       // broadcast, 8B
            int src32 = m.y & 0xFFFF;
            float tp = ushort_as_half_f((unsigned short)((unsigned)m.y >> 16));
            float Av = ldcg_half(Ain + src32 + lane);         // coalesced 64B, L2-coherent
            float ev = __half2float(__ldg(exb + m.x + lane)); // coalesced 64B, read-only
            acc = fmaf(Av, tp * ev, acc);
        }
        float val = acc * invm;
        Aout[state * BB + lane] = __float2half(val);

        // hierarchical per-batch max: block reduce, then padded atomicMax (non-neg floats as uint)
        sm[wid][lane] = val;
        __syncthreads();
        if (wid == 0) {
            float mx = sm[0][lane];
#pragma unroll
            for (int w = 1; w < WPB; w++) mx = fmaxf(mx, sm[w][lane]);
            atomicMax((unsigned*)&g_maxP[((t + 1) * BB + lane) * GMS], __float_as_uint(mx));
        }
        __threadfence();      // publish A stores + max atomics
        __syncthreads();

        // grid barrier (monotonic counter; all 250 blocks co-resident)
        if (threadIdx.x == 0) {
            atomicAdd(&g_bar, 1u);
            unsigned tgt = (unsigned)(NBLK * (t + 1));
            while (*(volatile unsigned*)&g_bar < tgt) __nanosleep(64);
            __threadfence();
        }
        __syncthreads();
    }

    // final reduction: deterministic, block 0 only. T even -> final alpha in buffer 0.
    if (blockIdx.x == 0) {
        const __half* __restrict__ AT = g_A[0];
        float part = 0.f;
        for (int s = wid; s < SS; s += WPB) part += ldcg_half(AT + s * BB + lane);
        sm[wid][lane] = part;
        __syncthreads();
        if (wid == 0) {
            float tot = sm[0][lane];
#pragma unroll
            for (int w = 1; w < WPB; w++) tot += sm[w][lane];
            float lt = logf(fmaxf(tot, 1e-38f));
            for (int t = 0; t < TT; t++)
                lt += logf(fmaxf(__ldcg(&g_maxP[(t * BB + lane) * GMS]), 1e-30f));
#pragma unroll
            for (int off = 16; off > 0; off >>= 1)
                lt += __shfl_xor_sync(0xffffffffu, lt, off);
            if (lane == 0) out[0] = lt / (float)BB;
        }
    }
}

// ---------------- entry ----------------
extern "C" void kernel_launch(void* const* d_in, const int* in_sizes, int n_in,
                              void* d_out, int out_size) {
    const float* x   = (const float*)d_in[0];  // [B,T,P]
    const float* lw  = (const float*)d_in[1];  // [E] log trans probs
    const float* ini = (const float*)d_in[2];  // [S] initial logprobs
    const int* src   = (const int*)d_in[3];    // [E]
    const int* dst   = (const int*)d_in[4];    // [E]
    const int* pdf   = (const int*)d_in[5];    // [E]
    float* out = (float*)d_out;

    k_zero<<<64, 256>>>();
    k_hist<<<(EE + 255) / 256, 256>>>(dst);
    k_scan<<<1, 256>>>();
    k_scatter<<<(EE + 255) / 256, 256>>>(src, dst, pdf, lw);
    k_initA<<<(SS * BB) / 256, 256>>>(ini);
    k_texp<<<dim3((PP + 31) / 32, TT), dim3(32, 8)>>>(x);
    k_main<<<NBLK, 256>>>(out);
}